// round 2
// baseline (speedup 1.0000x reference)
#include <cuda_runtime.h>

#define NL 50
#define THREADS 256
#define SPLITS 8          // blocks per batch row
#define MAX_PARTIAL 8192

__device__ float g_partial[MAX_PARTIAL];

// Pass 1: each block handles 1/SPLITS of one batch row, writes one partial sum.
__global__ __launch_bounds__(THREADS) void zws_partial_kernel(
    const float4* __restrict__ x,      // (B, V/2) float4 = 2 (z,val) pairs
    const float*  __restrict__ weight, // (NL,)
    int nf4_per_row)                   // V/2
{
    __shared__ float lo_s[NL + 2];
    __shared__ float hi_s[NL + 2];
    __shared__ float w_s[NL];

    const int tid = threadIdx.x;
    const int b   = blockIdx.x / SPLITS;
    const int s   = blockIdx.x % SPLITS;

    if (tid < NL) {
        // Bit-exact numpy edges: arange in double, /200*0.6, then cast f32.
        double lo_d = (tid < 25 ? (double)tid       : 25.0 + 7.0 * (tid - 25));
        double hi_d = (tid < 25 ? (double)(tid + 1) : 32.0 + 7.0 * (tid - 25));
        lo_s[tid + 1] = (float)(lo_d / 200.0 * 0.6);
        hi_s[tid + 1] = (float)(hi_d / 200.0 * 0.6);
        w_s[tid] = weight[tid];
    }
    if (tid == 0) {
        lo_s[0]      = 3.0e38f;  hi_s[0]      = -3.0e38f;
        lo_s[NL + 1] = 3.0e38f;  hi_s[NL + 1] = -3.0e38f;
    }
    __syncthreads();

    const int seg_len = (nf4_per_row + SPLITS - 1) / SPLITS;
    const int i_begin = s * seg_len;
    const int i_end   = min(i_begin + seg_len, nf4_per_row);

    const float4* row = x + (size_t)b * nf4_per_row;

    float acc = 0.0f;
    for (int i = i_begin + tid; i < i_end; i += THREADS) {
        float4 p = __ldg(&row[i]);
        {
            float z = p.x;
            float t = z * (200.0f / 0.6f);
            int c = (t < 25.0f) ? (int)t : 25 + (int)((t - 25.0f) * (1.0f / 7.0f));
            c = min(max(c, 0), NL - 1);
            float w = 0.0f;
            #pragma unroll
            for (int d = -1; d <= 1; ++d) {
                int j = c + d;
                if (z > lo_s[j + 1] && z < hi_s[j + 1]) w = w_s[j];
            }
            acc = fmaf(p.y, w, acc);
        }
        {
            float z = p.z;
            float t = z * (200.0f / 0.6f);
            int c = (t < 25.0f) ? (int)t : 25 + (int)((t - 25.0f) * (1.0f / 7.0f));
            c = min(max(c, 0), NL - 1);
            float w = 0.0f;
            #pragma unroll
            for (int d = -1; d <= 1; ++d) {
                int j = c + d;
                if (z > lo_s[j + 1] && z < hi_s[j + 1]) w = w_s[j];
            }
            acc = fmaf(p.w, w, acc);
        }
    }

    // Block reduction
    #pragma unroll
    for (int o = 16; o; o >>= 1)
        acc += __shfl_down_sync(0xFFFFFFFFu, acc, o);

    __shared__ float red[THREADS / 32];
    if ((tid & 31) == 0) red[tid >> 5] = acc;
    __syncthreads();

    if (tid < THREADS / 32) {
        float v = red[tid];
        #pragma unroll
        for (int o = (THREADS / 64); o; o >>= 1)
            v += __shfl_down_sync(0xFFu, v, o);
        if (tid == 0) g_partial[blockIdx.x] = v;
    }
}

// Pass 2: one block. Computes dot(bias, weight) once, then each thread b
// sums its SPLITS partials in fixed order (deterministic).
__global__ __launch_bounds__(THREADS) void zws_reduce_kernel(
    const float* __restrict__ weight,
    const float* __restrict__ bias,
    float*       __restrict__ out,
    int B)
{
    const int tid = threadIdx.x;

    // dot(bias, weight) over NL=50 terms, cooperative then broadcast.
    float d = (tid < NL) ? bias[tid] * weight[tid] : 0.0f;
    #pragma unroll
    for (int o = 16; o; o >>= 1)
        d += __shfl_down_sync(0xFFFFFFFFu, d, o);

    __shared__ float red[THREADS / 32];
    __shared__ float dot_s;
    if ((tid & 31) == 0) red[tid >> 5] = d;
    __syncthreads();
    if (tid == 0) {
        float t = 0.0f;
        #pragma unroll
        for (int i = 0; i < THREADS / 32; ++i) t += red[i];
        dot_s = t;
    }
    __syncthreads();

    for (int b = tid; b < B; b += THREADS) {
        float s = dot_s;
        #pragma unroll
        for (int k = 0; k < SPLITS; ++k)
            s += g_partial[b * SPLITS + k];
        out[b] = s;
    }
}

extern "C" void kernel_launch(void* const* d_in, const int* in_sizes, int n_in,
                              void* d_out, int out_size)
{
    const float4* x      = (const float4*)d_in[0];  // (B, V, 2) float32
    const float*  weight = (const float*)d_in[1];   // (NL, 1)
    const float*  bias   = (const float*)d_in[2];   // (NL,)
    float*        out    = (float*)d_out;           // (B,)

    const int B = out_size;                          // 256
    const int pairs_total = in_sizes[0] / 2;         // B * V
    const int nf4_per_row = pairs_total / B / 2;     // V / 2 = 2048

    zws_partial_kernel<<<B * SPLITS, THREADS>>>(x, weight, nf4_per_row);
    zws_reduce_kernel<<<1, THREADS>>>(weight, bias, out, B);
}

// round 3
// speedup vs baseline: 1.2941x; 1.2941x over previous
#include <cuda_runtime.h>

#define NL 50
#define THREADS 256
#define SPLITS 4            // blocks per batch row
#define MAX_B 4096

__device__ float        g_partial[MAX_B * SPLITS];
__device__ unsigned int g_count[MAX_B];   // zero-initialized; self-resetting

__global__ __launch_bounds__(THREADS) void zws_kernel(
    const float4* __restrict__ x,      // (B, V/2) float4 = 2 (z,val) pairs
    const float*  __restrict__ weight, // (NL,)
    const float*  __restrict__ bias,   // (NL,)
    float*        __restrict__ out,    // (B,)
    int nf4_per_row)                   // V/2
{
    __shared__ float lo_s[NL + 2];
    __shared__ float hi_s[NL + 2];
    __shared__ float w_s[NL];
    __shared__ bool  is_last;

    const int tid = threadIdx.x;
    const int b   = blockIdx.x / SPLITS;
    const int s   = blockIdx.x % SPLITS;

    float acc = 0.0f;

    if (tid < NL) {
        // Bit-exact numpy edges: arange in double, /200*0.6, cast to f32.
        double lo_d = (tid < 25 ? (double)tid       : 25.0 + 7.0 * (tid - 25));
        double hi_d = (tid < 25 ? (double)(tid + 1) : 32.0 + 7.0 * (tid - 25));
        lo_s[tid + 1] = (float)(lo_d / 200.0 * 0.6);
        hi_s[tid + 1] = (float)(hi_d / 200.0 * 0.6);
        float w = weight[tid];
        w_s[tid] = w;
        // dot(bias, weight) folded into block s==0's partial (fixed order).
        if (s == 0) acc = bias[tid] * w;
    }
    if (tid == 0) {
        lo_s[0]      = 3.0e38f;  hi_s[0]      = -3.0e38f;
        lo_s[NL + 1] = 3.0e38f;  hi_s[NL + 1] = -3.0e38f;
    }
    __syncthreads();

    const int seg_len = (nf4_per_row + SPLITS - 1) / SPLITS;
    const int i_begin = s * seg_len;
    const int i_end   = min(i_begin + seg_len, nf4_per_row);

    const float4* row = x + (size_t)b * nf4_per_row;

    #pragma unroll 2
    for (int i = i_begin + tid; i < i_end; i += THREADS) {
        float4 p = __ldg(&row[i]);
        {
            float z = p.x;
            float t = z * (200.0f / 0.6f);
            int c = (t < 25.0f) ? (int)t : 25 + (int)((t - 25.0f) * (1.0f / 7.0f));
            c = min(max(c, 0), NL - 1);
            float w = 0.0f;
            #pragma unroll
            for (int d = -1; d <= 1; ++d) {
                int j = c + d;
                if (z > lo_s[j + 1] && z < hi_s[j + 1]) w = w_s[j];
            }
            acc = fmaf(p.y, w, acc);
        }
        {
            float z = p.z;
            float t = z * (200.0f / 0.6f);
            int c = (t < 25.0f) ? (int)t : 25 + (int)((t - 25.0f) * (1.0f / 7.0f));
            c = min(max(c, 0), NL - 1);
            float w = 0.0f;
            #pragma unroll
            for (int d = -1; d <= 1; ++d) {
                int j = c + d;
                if (z > lo_s[j + 1] && z < hi_s[j + 1]) w = w_s[j];
            }
            acc = fmaf(p.w, w, acc);
        }
    }

    // Block reduction
    #pragma unroll
    for (int o = 16; o; o >>= 1)
        acc += __shfl_down_sync(0xFFFFFFFFu, acc, o);

    __shared__ float red[THREADS / 32];
    if ((tid & 31) == 0) red[tid >> 5] = acc;
    __syncthreads();

    if (tid == 0) {
        float v = 0.0f;
        #pragma unroll
        for (int i = 0; i < THREADS / 32; ++i) v += red[i];
        g_partial[b * SPLITS + s] = v;
        __threadfence();
        unsigned int old = atomicAdd(&g_count[b], 1u);
        is_last = (old == SPLITS - 1);
    }
    __syncthreads();

    // Last block of this row: sum the SPLITS partials in fixed order.
    if (is_last && tid == 0) {
        __threadfence();
        volatile float* vp = &g_partial[b * SPLITS];
        float total = 0.0f;
        #pragma unroll
        for (int k = 0; k < SPLITS; ++k) total += vp[k];
        out[b] = total;
        g_count[b] = 0;   // reset for next graph replay
    }
}

extern "C" void kernel_launch(void* const* d_in, const int* in_sizes, int n_in,
                              void* d_out, int out_size)
{
    const float4* x      = (const float4*)d_in[0];  // (B, V, 2) float32
    const float*  weight = (const float*)d_in[1];   // (NL, 1)
    const float*  bias   = (const float*)d_in[2];   // (NL,)
    float*        out    = (float*)d_out;           // (B,)

    const int B = out_size;                          // 256
    const int pairs_total = in_sizes[0] / 2;         // B * V
    const int nf4_per_row = pairs_total / B / 2;     // V / 2 = 2048

    zws_kernel<<<B * SPLITS, THREADS>>>(x, weight, bias, out, nf4_per_row);
}

// round 4
// speedup vs baseline: 1.9412x; 1.5000x over previous
#include <cuda_runtime.h>

#define NL 50
#define THREADS 256
#define SPLITS 4
#define MAX_B 4096

// Edge integers: E_i = i for i<=25, else 25 + 7*(i-25); E_50 = 200.
// Edge floats computed exactly as numpy: (double)n / 200.0 * 0.6, cast to f32.
constexpr int   edge_int(int i) { return i <= 25 ? i : 25 + 7 * (i - 25); }
constexpr float edge_f(int i)   { return (float)((double)edge_int(i) / 200.0 * 0.6); }

#define E1(a)  edge_f(a)
#define E4(a)  E1(a), E1(a+1), E1(a+2), E1(a+3)
#define E16(a) E4(a), E4(a+4), E4(a+8), E4(a+12)
__constant__ float c_edges[51] = { E16(0), E16(16), E16(32), E1(48), E1(49), E1(50) };

__device__ float        g_partial[MAX_B * SPLITS];
__device__ unsigned int g_count[MAX_B];   // zero-init; self-resetting

// se: 53 entries. se[0]=+BIG sentinel, se[1..51]=E_0..E_50, se[52]=-BIG sentinel.
// Bin j (0..49): low=se[j+1], high=se[j+2]. Weight sw[j+1], sw[0]=sw[51]=0.
__device__ __forceinline__ float bin_weight(float z,
                                            const float* __restrict__ se,
                                            const float* __restrict__ sw)
{
    float t = z * (200.0f / 0.6f);
    int c = (t < 25.0f) ? (int)t : 25 + (int)((t - 25.0f) * (1.0f / 7.0f));
    c = min(max(c, 0), NL - 1);
    float e0 = se[c], e1 = se[c + 1], e2 = se[c + 2], e3 = se[c + 3];
    int jm = -1;                                  // sw[0] = 0 -> no match
    if (z > e0 && z < e1) jm = c - 1;
    if (z > e1 && z < e2) jm = c;
    if (z > e2 && z < e3) jm = c + 1;
    return sw[jm + 1];
}

__global__ __launch_bounds__(THREADS) void zws_kernel(
    const float4* __restrict__ x,      // (B, V/2) float4 = 2 (z,val) pairs
    const float*  __restrict__ weight, // (NL,)
    const float*  __restrict__ bias,   // (NL,)
    float*        __restrict__ out,    // (B,)
    int nf4_per_row)                   // V/2
{
    __shared__ float se[53];
    __shared__ float sw[52];
    __shared__ bool  is_last;

    const int tid = threadIdx.x;
    const int b   = blockIdx.x / SPLITS;
    const int s   = blockIdx.x % SPLITS;

    if (tid < 53)
        se[tid] = (tid == 0) ? 3.0e38f : (tid == 52 ? -3.0e38f : c_edges[tid - 1]);
    if (tid < 52)
        sw[tid] = (tid == 0 || tid == 51) ? 0.0f : weight[tid - 1];

    float acc = 0.0f;
    if (s == 0 && tid < NL)                    // fold dot(bias, weight) once
        acc = bias[tid] * weight[tid];
    __syncthreads();

    const int seg_len = (nf4_per_row + SPLITS - 1) / SPLITS;
    const int i_begin = s * seg_len;
    const int i_end   = min(i_begin + seg_len, nf4_per_row);

    const float4* row = x + (size_t)b * nf4_per_row;

    for (int i = i_begin + tid; i < i_end; i += 2 * THREADS) {
        // Batch both loads up-front (MLP), dependent work after.
        float4 p0 = __ldg(&row[i]);
        float4 p1 = make_float4(0.0f, 0.0f, 0.0f, 0.0f);
        if (i + THREADS < i_end) p1 = __ldg(&row[i + THREADS]);

        acc = fmaf(p0.y, bin_weight(p0.x, se, sw), acc);
        acc = fmaf(p0.w, bin_weight(p0.z, se, sw), acc);
        acc = fmaf(p1.y, bin_weight(p1.x, se, sw), acc);
        acc = fmaf(p1.w, bin_weight(p1.z, se, sw), acc);
    }

    // Block reduction
    #pragma unroll
    for (int o = 16; o; o >>= 1)
        acc += __shfl_down_sync(0xFFFFFFFFu, acc, o);

    __shared__ float red[THREADS / 32];
    if ((tid & 31) == 0) red[tid >> 5] = acc;
    __syncthreads();

    if (tid == 0) {
        float v = 0.0f;
        #pragma unroll
        for (int i = 0; i < THREADS / 32; ++i) v += red[i];
        g_partial[b * SPLITS + s] = v;
        __threadfence();
        unsigned int old = atomicAdd(&g_count[b], 1u);
        is_last = (old == SPLITS - 1);
    }
    __syncthreads();

    if (is_last && tid == 0) {
        __threadfence();
        volatile float* vp = &g_partial[b * SPLITS];
        float total = 0.0f;
        #pragma unroll
        for (int k = 0; k < SPLITS; ++k) total += vp[k];
        out[b] = total;
        g_count[b] = 0;   // reset for next graph replay
    }
}

extern "C" void kernel_launch(void* const* d_in, const int* in_sizes, int n_in,
                              void* d_out, int out_size)
{
    const float4* x      = (const float4*)d_in[0];  // (B, V, 2) float32
    const float*  weight = (const float*)d_in[1];   // (NL, 1)
    const float*  bias   = (const float*)d_in[2];   // (NL,)
    float*        out    = (float*)d_out;           // (B,)

    const int B = out_size;                          // 256
    const int pairs_total = in_sizes[0] / 2;         // B * V
    const int nf4_per_row = pairs_total / B / 2;     // V / 2 = 2048

    zws_kernel<<<B * SPLITS, THREADS>>>(x, weight, bias, out, nf4_per_row);
}